// round 1
// baseline (speedup 1.0000x reference)
#include <cuda_runtime.h>

#define NN   100000   // nodes
#define NPAD 100096   // 782 * 128
#define EE   1000000  // edges per relation
#define RR   4        // relations
#define GG   256      // graphs
#define DH   128
#define NC   10

// ---------------- scratch (device globals; no allocation in kernel_launch) ----
__device__ int   g_deg_in [RR][NN];
__device__ int   g_deg_out[RR][NN];
__device__ float g_rs_in  [RR][NN];
__device__ float g_rs_out [RR][NN];
__device__ int   g_rowoff [RR][NN + 1];
__device__ int   g_cursor [RR][NN];
__device__ int   g_csr    [RR][EE];
__device__ float g_M [(size_t)NPAD * 512];   // concatenated messages [N, R*128]
__device__ float g_h0[(size_t)NPAD * DH];
__device__ float g_h1[(size_t)NPAD * DH];
__device__ int   g_gstart[GG + 1];

// ---------------- init / degree / csr ----------------------------------------
__global__ void k_zero() {
    int i = blockIdx.x * blockDim.x + threadIdx.x;
    if (i < RR * NN) {
        ((int*)g_deg_in)[i]  = 0;
        ((int*)g_deg_out)[i] = 0;
    }
    if (i <= GG) g_gstart[i] = NN;
}

__global__ void k_deg(const int* __restrict__ edges) {
    int i = blockIdx.x * blockDim.x + threadIdx.x;
    if (i >= RR * EE) return;
    int r = i / EE, e = i - r * EE;
    int src = edges[(size_t)r * 2 * EE + e];
    int dst = edges[(size_t)r * 2 * EE + EE + e];
    atomicAdd(&g_deg_out[r][src], 1);
    atomicAdd(&g_deg_in [r][dst], 1);
}

__global__ void k_rs() {
    int i = blockIdx.x * blockDim.x + threadIdx.x;
    if (i >= RR * NN) return;
    int r = i / NN, n = i - r * NN;
    g_rs_out[r][n] = rsqrtf((float)max(g_deg_out[r][n], 1));
    g_rs_in [r][n] = rsqrtf((float)max(g_deg_in [r][n], 1));
}

// exclusive scan of deg_in per relation -> rowoff, cursor. One block per relation.
__global__ void k_scan() {
    int r = blockIdx.x;
    __shared__ int ws[32];
    __shared__ int s_base;
    int tid = threadIdx.x, lane = tid & 31, wid = tid >> 5;
    if (tid == 0) s_base = 0;
    __syncthreads();
    for (int c0 = 0; c0 < NN; c0 += 1024) {
        int idx = c0 + tid;
        int v = (idx < NN) ? g_deg_in[r][idx] : 0;
        int x = v;
        #pragma unroll
        for (int o = 1; o < 32; o <<= 1) {
            int y = __shfl_up_sync(0xffffffffu, x, o);
            if (lane >= o) x += y;
        }
        if (lane == 31) ws[wid] = x;
        __syncthreads();
        if (wid == 0) {
            int s = ws[lane];
            #pragma unroll
            for (int o = 1; o < 32; o <<= 1) {
                int y = __shfl_up_sync(0xffffffffu, s, o);
                if (lane >= o) s += y;
            }
            ws[lane] = s;
        }
        __syncthreads();
        int base = s_base;
        int add  = (wid > 0) ? ws[wid - 1] : 0;
        int excl = base + add + x - v;
        if (idx < NN) { g_rowoff[r][idx] = excl; g_cursor[r][idx] = excl; }
        __syncthreads();
        if (tid == 0) s_base += ws[31];
        __syncthreads();
    }
    if (tid == 0) g_rowoff[r][NN] = s_base;
}

__global__ void k_fill(const int* __restrict__ edges) {
    int i = blockIdx.x * blockDim.x + threadIdx.x;
    if (i >= RR * EE) return;
    int r = i / EE, e = i - r * EE;
    int src = edges[(size_t)r * 2 * EE + e];
    int dst = edges[(size_t)r * 2 * EE + EE + e];
    int pos = atomicAdd(&g_cursor[r][dst], 1);
    g_csr[r][pos] = src;
}

__global__ void k_gstart(const int* __restrict__ gid) {
    int n = blockIdx.x * blockDim.x + threadIdx.x;
    if (n >= NN) return;
    int g = gid[n];
    int p = (n == 0) ? -1 : gid[n - 1];
    for (int x = p + 1; x <= g; x++) g_gstart[x] = n;
}

// ---------------- aggregation: pull per dst node, 1 warp per node -------------
__global__ __launch_bounds__(256) void k_agg(const float* __restrict__ hin) {
    int w    = (blockIdx.x * 256 + threadIdx.x) >> 5;   // node id
    int lane = threadIdx.x & 31;
    if (w >= NN) return;
    const float4* __restrict__ h4 = (const float4*)hin;
    float4* __restrict__ M4 = (float4*)g_M;
    #pragma unroll
    for (int r = 0; r < RR; r++) {
        int e0 = g_rowoff[r][w], e1 = g_rowoff[r][w + 1];
        float4 acc = make_float4(0.f, 0.f, 0.f, 0.f);
        for (int e = e0; e < e1; e++) {
            int   s  = g_csr[r][e];
            float sw = g_rs_out[r][s];
            float4 v = __ldg(&h4[(size_t)s * 32 + lane]);
            acc.x += sw * v.x; acc.y += sw * v.y;
            acc.z += sw * v.z; acc.w += sw * v.w;
        }
        float wi = g_rs_in[r][w];
        acc.x *= wi; acc.y *= wi; acc.z *= wi; acc.w *= wi;
        M4[(size_t)w * 128 + r * 32 + lane] = acc;
    }
}

// ---------------- GEMM: C[NPAD,128] = relu(M[NPAD,512] @ W[512,128] + sum_r b)
__global__ __launch_bounds__(256) void k_gemm(const float* __restrict__ W,
                                              const float* __restrict__ bias,
                                              float* __restrict__ C) {
    __shared__ float As[8][128];
    __shared__ float Bs[8][128];
    int tid = threadIdx.x;
    int tx = tid & 15, ty = tid >> 4;          // 16x16 threads, 8x8 micro-tile
    int m0 = blockIdx.x * 128;

    int arow = tid >> 1, apart = tid & 1;      // A tile loader: 128 rows x 8 k
    int brow = tid >> 5, bcol = (tid & 31) * 4;

    float acc[8][8];
    #pragma unroll
    for (int i = 0; i < 8; i++)
        #pragma unroll
        for (int j = 0; j < 8; j++) acc[i][j] = 0.f;

    const float* A = g_M;
    for (int k0 = 0; k0 < 512; k0 += 8) {
        float4 av = *(const float4*)&A[(size_t)(m0 + arow) * 512 + k0 + apart * 4];
        float4 bv = *(const float4*)&W[(size_t)(k0 + brow) * 128 + bcol];
        __syncthreads();
        As[apart * 4 + 0][arow] = av.x;
        As[apart * 4 + 1][arow] = av.y;
        As[apart * 4 + 2][arow] = av.z;
        As[apart * 4 + 3][arow] = av.w;
        *(float4*)&Bs[brow][bcol] = bv;
        __syncthreads();
        #pragma unroll
        for (int k = 0; k < 8; k++) {
            float ar[8], br[8];
            #pragma unroll
            for (int i = 0; i < 8; i++) ar[i] = As[k][ty * 8 + i];
            #pragma unroll
            for (int j = 0; j < 8; j++) br[j] = Bs[k][tx * 8 + j];
            #pragma unroll
            for (int i = 0; i < 8; i++)
                #pragma unroll
                for (int j = 0; j < 8; j++) acc[i][j] += ar[i] * br[j];
        }
    }

    float bs[8];
    #pragma unroll
    for (int j = 0; j < 8; j++) {
        int c = tx * 8 + j;
        bs[j] = bias[c] + bias[128 + c] + bias[256 + c] + bias[384 + c];
    }
    #pragma unroll
    for (int i = 0; i < 8; i++) {
        int row = m0 + ty * 8 + i;
        float4 o0, o1;
        o0.x = fmaxf(acc[i][0] + bs[0], 0.f);
        o0.y = fmaxf(acc[i][1] + bs[1], 0.f);
        o0.z = fmaxf(acc[i][2] + bs[2], 0.f);
        o0.w = fmaxf(acc[i][3] + bs[3], 0.f);
        o1.x = fmaxf(acc[i][4] + bs[4], 0.f);
        o1.y = fmaxf(acc[i][5] + bs[5], 0.f);
        o1.z = fmaxf(acc[i][6] + bs[6], 0.f);
        o1.w = fmaxf(acc[i][7] + bs[7], 0.f);
        *(float4*)&C[(size_t)row * 128 + tx * 8]     = o0;
        *(float4*)&C[(size_t)row * 128 + tx * 8 + 4] = o1;
    }
}

// ---------------- fused avg-pool + classifier ---------------------------------
__global__ void k_pool(const float* __restrict__ h,
                       const float* __restrict__ Wc,
                       const float* __restrict__ bc,
                       float* __restrict__ out) {
    int g = blockIdx.x;
    int k = threadIdx.x;   // 128 threads
    int lo = g_gstart[g], hi = g_gstart[g + 1];
    float s = 0.f;
    for (int n = lo; n < hi; n++) s += h[(size_t)n * 128 + k];
    float cnt = (float)max(hi - lo, 1);
    __shared__ float sh[128];
    sh[k] = s / cnt;
    __syncthreads();
    if (k < NC) {
        float a = bc[k];
        #pragma unroll 16
        for (int j = 0; j < 128; j++) a += sh[j] * Wc[j * NC + k];
        out[g * NC + k] = a;
    }
}

// ---------------- launcher ----------------------------------------------------
extern "C" void kernel_launch(void* const* d_in, const int* in_sizes, int n_in,
                              void* d_out, int out_size) {
    const float* features = (const float*)d_in[0];
    const int*   edges    = (const int*)  d_in[1];
    const int*   gid      = (const int*)  d_in[2];
    const float* W0       = (const float*)d_in[3];
    const float* b0       = (const float*)d_in[4];
    const float* Wl       = (const float*)d_in[5];
    const float* bl       = (const float*)d_in[6];
    const float* Wc       = (const float*)d_in[7];
    const float* bc       = (const float*)d_in[8];
    float* out = (float*)d_out;

    float *h0p = nullptr, *h1p = nullptr;
    cudaGetSymbolAddress((void**)&h0p, g_h0);
    cudaGetSymbolAddress((void**)&h1p, g_h1);

    // graph structure (once per launch, reused by all 3 layers)
    k_zero  <<<(RR * NN + 255) / 256, 256>>>();
    k_deg   <<<(RR * EE + 255) / 256, 256>>>(edges);
    k_rs    <<<(RR * NN + 255) / 256, 256>>>();
    k_scan  <<<RR, 1024>>>();
    k_fill  <<<(RR * EE + 255) / 256, 256>>>(edges);
    k_gstart<<<(NN + 255) / 256, 256>>>(gid);

    // layer 0: features -> h0
    k_agg <<<NN / 8, 256>>>(features);
    k_gemm<<<NPAD / 128, 256>>>(W0, b0, h0p);
    // layer 1: h0 -> h1
    k_agg <<<NN / 8, 256>>>(h0p);
    k_gemm<<<NPAD / 128, 256>>>(Wl, bl, h1p);
    // layer 2: h1 -> h0
    k_agg <<<NN / 8, 256>>>(h1p);
    k_gemm<<<NPAD / 128, 256>>>(Wl + (size_t)RR * DH * DH, bl + (size_t)RR * DH, h0p);

    // pool + classify
    k_pool<<<GG, 128>>>(h0p, Wc, bc, out);
}

// round 4
// speedup vs baseline: 1.3491x; 1.3491x over previous
#include <cuda_runtime.h>
#include <mma.h>
#include <cstdint>

using namespace nvcuda;

#define NN   100000   // nodes
#define NPAD 100096   // 782 * 128
#define EE   1000000  // edges per relation
#define RR   4        // relations
#define GG   256      // graphs
#define DH   128
#define NC   10

#define SCH  512
#define SNB  196      // ceil(NN/SCH)

// ---------------- scratch (device globals; no allocation in kernel_launch) ----
__device__ int   g_deg_in [RR][NN];
__device__ int   g_deg_out[RR][NN];
__device__ float g_rs_in  [RR][NN];
__device__ float g_rs_out [RR][NN];
__device__ int   g_rowoff [RR][NN + 1];
__device__ int   g_cursor [RR][NN];
__device__ int   g_csr    [RR][EE];
__device__ int   g_bsum   [RR][SNB];
__device__ float g_M [(size_t)NPAD * 512];   // concatenated messages [N, R*128]
__device__ float g_h0[(size_t)NPAD * DH];
__device__ float g_h1[(size_t)NPAD * DH];
__device__ float g_Wt[3][128][512];          // per-layer W^T, tf32-rounded
__device__ int   g_gstart[GG + 1];

__device__ __forceinline__ uint32_t f2tf32(float f) {
    uint32_t u; asm("cvt.rna.tf32.f32 %0, %1;" : "=r"(u) : "f"(f)); return u;
}

// ---------------- init / degree / csr ----------------------------------------
__global__ void k_zero() {
    int i = blockIdx.x * blockDim.x + threadIdx.x;
    if (i < RR * NN) {
        ((int*)g_deg_in)[i]  = 0;
        ((int*)g_deg_out)[i] = 0;
    }
    if (i <= GG) g_gstart[i] = NN;
}

__global__ void k_deg(const int* __restrict__ edges) {
    int i = blockIdx.x * blockDim.x + threadIdx.x;
    if (i >= RR * EE) return;
    int r = i / EE, e = i - r * EE;
    int src = edges[(size_t)r * 2 * EE + e];
    int dst = edges[(size_t)r * 2 * EE + EE + e];
    atomicAdd(&g_deg_out[r][src], 1);
    atomicAdd(&g_deg_in [r][dst], 1);
}

__global__ void k_rs() {
    int i = blockIdx.x * blockDim.x + threadIdx.x;
    if (i >= RR * NN) return;
    int r = i / NN, n = i - r * NN;
    g_rs_out[r][n] = rsqrtf((float)max(g_deg_out[r][n], 1));
    g_rs_in [r][n] = rsqrtf((float)max(g_deg_in [r][n], 1));
}

__device__ __forceinline__ int blockExclScan(int v, int* ws, int nwarp) {
    int tid = threadIdx.x, lane = tid & 31, wid = tid >> 5;
    int x = v;
    #pragma unroll
    for (int o = 1; o < 32; o <<= 1) {
        int y = __shfl_up_sync(0xffffffffu, x, o);
        if (lane >= o) x += y;
    }
    if (lane == 31) ws[wid] = x;
    __syncthreads();
    if (wid == 0) {
        int s = (lane < nwarp) ? ws[lane] : 0;
        #pragma unroll
        for (int o = 1; o < 32; o <<= 1) {
            int y = __shfl_up_sync(0xffffffffu, s, o);
            if (lane >= o) s += y;
        }
        if (lane < nwarp) ws[lane] = s;
    }
    __syncthreads();
    int add = (wid > 0) ? ws[wid - 1] : 0;
    return add + x - v;
}

// phase 1: per-block sums of deg_in chunks
__global__ void k_scan1() {
    int r = blockIdx.y, b = blockIdx.x;
    int i0 = b * SCH;
    int s = 0;
    for (int i = threadIdx.x; i < SCH; i += 256) {
        int idx = i0 + i;
        if (idx < NN) s += g_deg_in[r][idx];
    }
    __shared__ int ws[8];
    int lane = threadIdx.x & 31, wid = threadIdx.x >> 5;
    #pragma unroll
    for (int o = 16; o > 0; o >>= 1) s += __shfl_down_sync(0xffffffffu, s, o);
    if (lane == 0) ws[wid] = s;
    __syncthreads();
    if (threadIdx.x == 0) {
        int t = 0;
        #pragma unroll
        for (int w = 0; w < 8; w++) t += ws[w];
        g_bsum[r][b] = t;
    }
}

// phase 2: exclusive scan of block sums (one block per relation)
__global__ void k_scan2() {
    int r = blockIdx.x, tid = threadIdx.x;
    __shared__ int ws[8];
    int v = (tid < SNB) ? g_bsum[r][tid] : 0;
    int ex = blockExclScan(v, ws, 8);
    if (tid < SNB) g_bsum[r][tid] = ex;
    if (tid == SNB - 1) g_rowoff[r][NN] = ex + v;
}

// phase 3: per-chunk scan + block offset
__global__ void k_scan3() {
    int r = blockIdx.y, b = blockIdx.x;
    int idx = b * SCH + threadIdx.x;
    __shared__ int ws[16];
    int v = (idx < NN) ? g_deg_in[r][idx] : 0;
    int ex = blockExclScan(v, ws, 16) + g_bsum[r][b];
    if (idx < NN) { g_rowoff[r][idx] = ex; g_cursor[r][idx] = ex; }
}

__global__ void k_fill(const int* __restrict__ edges) {
    int i = blockIdx.x * blockDim.x + threadIdx.x;
    if (i >= RR * EE) return;
    int r = i / EE, e = i - r * EE;
    int src = edges[(size_t)r * 2 * EE + e];
    int dst = edges[(size_t)r * 2 * EE + EE + e];
    int pos = atomicAdd(&g_cursor[r][dst], 1);
    g_csr[r][pos] = src;
}

__global__ void k_gstart(const int* __restrict__ gid) {
    int n = blockIdx.x * blockDim.x + threadIdx.x;
    if (n >= NN) return;
    int g = gid[n];
    int p = (n == 0) ? -1 : gid[n - 1];
    for (int x = p + 1; x <= g; x++) g_gstart[x] = n;
}

// weight prep: Wt[l][n][k] = rna_tf32(W_l[k][n])
__global__ void k_wprep(const float* __restrict__ W0, const float* __restrict__ Wl) {
    int idx = blockIdx.x * 256 + threadIdx.x;   // 3*128*512
    if (idx >= 3 * 128 * 512) return;
    int l = idx >> 16;
    int rem = idx & 65535;
    int n = rem >> 9;
    int k = rem & 511;
    const float* W = (l == 0) ? W0 : (Wl + (size_t)(l - 1) * 65536);
    ((uint32_t*)g_Wt)[idx] = f2tf32(W[(size_t)k * 128 + n]);
}

// ---------------- aggregation: pull per dst node, 1 warp per node -------------
__global__ __launch_bounds__(256) void k_agg(const float* __restrict__ hin) {
    int w    = (blockIdx.x * 256 + threadIdx.x) >> 5;   // node id
    int lane = threadIdx.x & 31;
    if (w >= NN) return;
    const float4* __restrict__ h4 = (const float4*)hin;
    float4* __restrict__ M4 = (float4*)g_M;
    #pragma unroll
    for (int r = 0; r < RR; r++) {
        int e0 = g_rowoff[r][w], e1 = g_rowoff[r][w + 1];
        float4 acc = make_float4(0.f, 0.f, 0.f, 0.f);
        for (int e = e0; e < e1; e++) {
            int   s  = g_csr[r][e];
            float sw = g_rs_out[r][s];
            float4 v = __ldg(&h4[(size_t)s * 32 + lane]);
            acc.x += sw * v.x; acc.y += sw * v.y;
            acc.z += sw * v.z; acc.w += sw * v.w;
        }
        float wi = g_rs_in[r][w];
        acc.x *= wi; acc.y *= wi; acc.z *= wi; acc.w *= wi;
        M4[(size_t)w * 128 + r * 32 + lane] = acc;
    }
}

// ---------------- WMMA tf32 GEMM: C[NPAD,128] = relu(M @ Wt^T + sum_r b) ------
// Block tile 128x128, K chunked by 32. 8 warps, warp tile 32(m) x 64(n),
// fragments m16n16k8 tf32. Epilogue fused via per-warp SMEM staging (reuses As).
#define LDT 40
#define SLD 20    // epilogue staging ldm: 80 bytes, multiple of 16B (WMMA req)

__global__ __launch_bounds__(256, 2) void k_gemm_mma(const float* __restrict__ Bt,
                                                     const float* __restrict__ bias,
                                                     float* __restrict__ C) {
    __shared__ float As[128 * LDT];
    __shared__ float Bs[128 * LDT];
    __shared__ float sh_bias[128];

    int tid = threadIdx.x;
    int m0  = blockIdx.x * 128;
    int wid = tid >> 5, lane = tid & 31;
    int wm = wid & 3, wn = wid >> 2;       // 4 warps in m, 2 in n

    if (tid < 128)
        sh_bias[tid] = bias[tid] + bias[128 + tid] + bias[256 + tid] + bias[384 + tid];

    wmma::fragment<wmma::accumulator, 16, 16, 8, float> acc[2][4];
    #pragma unroll
    for (int mi = 0; mi < 2; mi++)
        #pragma unroll
        for (int ni = 0; ni < 4; ni++) wmma::fill_fragment(acc[mi][ni], 0.0f);

    const float* A = g_M;

    for (int ch = 0; ch < 16; ch++) {
        int k0 = ch * 32;
        #pragma unroll
        for (int i = 0; i < 4; i++) {
            int s   = tid + i * 256;        // 0..1023 float4 slots
            int row = s >> 3;
            int kq  = (s & 7) << 2;
            float4 v = __ldg((const float4*)&A[(size_t)(m0 + row) * 512 + k0 + kq]);
            uint4 u;
            u.x = f2tf32(v.x); u.y = f2tf32(v.y);
            u.z = f2tf32(v.z); u.w = f2tf32(v.w);
            *(uint4*)&As[row * LDT + kq] = u;
            // Bt already tf32-rounded by k_wprep
            *(float4*)&Bs[row * LDT + kq] =
                __ldg((const float4*)&Bt[(size_t)row * 512 + k0 + kq]);
        }
        __syncthreads();
        #pragma unroll
        for (int ks = 0; ks < 4; ks++) {
            wmma::fragment<wmma::matrix_a, 16, 16, 8, wmma::precision::tf32,
                           wmma::row_major> af[2];
            wmma::fragment<wmma::matrix_b, 16, 16, 8, wmma::precision::tf32,
                           wmma::col_major> bf[4];
            #pragma unroll
            for (int mi = 0; mi < 2; mi++)
                wmma::load_matrix_sync(af[mi],
                    &As[(wm * 32 + mi * 16) * LDT + ks * 8], LDT);
            #pragma unroll
            for (int ni = 0; ni < 4; ni++)
                wmma::load_matrix_sync(bf[ni],
                    &Bs[(wn * 64 + ni * 16) * LDT + ks * 8], LDT);
            #pragma unroll
            for (int mi = 0; mi < 2; mi++)
                #pragma unroll
                for (int ni = 0; ni < 4; ni++)
                    wmma::mma_sync(acc[mi][ni], af[mi], bf[ni], acc[mi][ni]);
        }
        __syncthreads();
    }

    // epilogue: stage each 16x16 frag in SMEM (reuse As), add bias, relu, store
    float* stg = As + wid * (16 * SLD);
    int r  = lane >> 1;
    int c0 = (lane & 1) * 8;
    #pragma unroll
    for (int mi = 0; mi < 2; mi++) {
        #pragma unroll
        for (int ni = 0; ni < 4; ni++) {
            wmma::store_matrix_sync(stg, acc[mi][ni], SLD, wmma::mem_row_major);
            __syncwarp();
            int grow = m0 + wm * 32 + mi * 16 + r;
            int gcol = wn * 64 + ni * 16 + c0;
            float4 o0, o1;
            o0.x = fmaxf(stg[r * SLD + c0 + 0] + sh_bias[gcol + 0], 0.f);
            o0.y = fmaxf(stg[r * SLD + c0 + 1] + sh_bias[gcol + 1], 0.f);
            o0.z = fmaxf(stg[r * SLD + c0 + 2] + sh_bias[gcol + 2], 0.f);
            o0.w = fmaxf(stg[r * SLD + c0 + 3] + sh_bias[gcol + 3], 0.f);
            o1.x = fmaxf(stg[r * SLD + c0 + 4] + sh_bias[gcol + 4], 0.f);
            o1.y = fmaxf(stg[r * SLD + c0 + 5] + sh_bias[gcol + 5], 0.f);
            o1.z = fmaxf(stg[r * SLD + c0 + 6] + sh_bias[gcol + 6], 0.f);
            o1.w = fmaxf(stg[r * SLD + c0 + 7] + sh_bias[gcol + 7], 0.f);
            *(float4*)&C[(size_t)grow * 128 + gcol]     = o0;
            *(float4*)&C[(size_t)grow * 128 + gcol + 4] = o1;
            __syncwarp();
        }
    }
}

// ---------------- fused avg-pool + classifier ---------------------------------
__global__ void k_pool(const float* __restrict__ h,
                       const float* __restrict__ Wc,
                       const float* __restrict__ bc,
                       float* __restrict__ out) {
    int g = blockIdx.x;
    int k = threadIdx.x;   // 128 threads
    int lo = g_gstart[g], hi = g_gstart[g + 1];
    float s = 0.f;
    for (int n = lo; n < hi; n++) s += h[(size_t)n * 128 + k];
    float cnt = (float)max(hi - lo, 1);
    __shared__ float sh[128];
    sh[k] = s / cnt;
    __syncthreads();
    if (k < NC) {
        float a = bc[k];
        #pragma unroll 16
        for (int j = 0; j < 128; j++) a += sh[j] * Wc[j * NC + k];
        out[g * NC + k] = a;
    }
}

// ---------------- launcher ----------------------------------------------------
extern "C" void kernel_launch(void* const* d_in, const int* in_sizes, int n_in,
                              void* d_out, int out_size) {
    const float* features = (const float*)d_in[0];
    const int*   edges    = (const int*)  d_in[1];
    const int*   gid      = (const int*)  d_in[2];
    const float* W0       = (const float*)d_in[3];
    const float* b0       = (const float*)d_in[4];
    const float* Wl       = (const float*)d_in[5];
    const float* bl       = (const float*)d_in[6];
    const float* Wc       = (const float*)d_in[7];
    const float* bc       = (const float*)d_in[8];
    float* out = (float*)d_out;

    float *h0p = nullptr, *h1p = nullptr, *wtp = nullptr;
    cudaGetSymbolAddress((void**)&h0p, g_h0);
    cudaGetSymbolAddress((void**)&h1p, g_h1);
    cudaGetSymbolAddress((void**)&wtp, g_Wt);

    // graph structure (once per launch, reused by all 3 layers)
    k_zero  <<<(RR * NN + 255) / 256, 256>>>();
    k_deg   <<<(RR * EE + 255) / 256, 256>>>(edges);
    k_rs    <<<(RR * NN + 255) / 256, 256>>>();
    k_scan1 <<<dim3(SNB, RR), 256>>>();
    k_scan2 <<<RR, 256>>>();
    k_scan3 <<<dim3(SNB, RR), 512>>>();
    k_fill  <<<(RR * EE + 255) / 256, 256>>>(edges);
    k_gstart<<<(NN + 255) / 256, 256>>>(gid);
    k_wprep <<<(3 * 128 * 512 + 255) / 256, 256>>>(W0, Wl);

    // layer 0: features -> h0
    k_agg     <<<NN / 8, 256>>>(features);
    k_gemm_mma<<<NPAD / 128, 256>>>(wtp, b0, h0p);
    // layer 1: h0 -> h1
    k_agg     <<<NN / 8, 256>>>(h0p);
    k_gemm_mma<<<NPAD / 128, 256>>>(wtp + 65536, bl, h1p);
    // layer 2: h1 -> h0
    k_agg     <<<NN / 8, 256>>>(h1p);
    k_gemm_mma<<<NPAD / 128, 256>>>(wtp + 2 * 65536, bl + 512, h0p);

    // pool + classify
    k_pool<<<GG, 128>>>(h0p, Wc, bc, out);
}